// round 1
// baseline (speedup 1.0000x reference)
#include <cuda_runtime.h>
#include <cstdint>

// VectorQuantizer: N=262144 inputs [N,64] f32, codebook [1024,64] f32.
// dist = x_sq - 2*x.c + c_sq ; out[row] = codebook[argmin(dist)].
// Strategy (round 0): fp32-exact distances using packed fma.rn.f32x2 (FFMA2).
//   - 2 rows per thread held fully in registers (64 f32x2 pairs)
//   - codebook staged in smem in 128-code chunks, warp-uniform broadcast LDS
//   - 8-code accumulator sub-batches -> 16 FFMA2 per 8 LDS per k-pair
//   - strict < argmin with ascending code order (matches argmin first-index ties)

#define N_DIM      64
#define KP         32          // k-pairs (f32x2)
#define NCODES     1024
#define BLOCK      256
#define RPT        2           // rows per thread
#define ROWS_PER_BLOCK (BLOCK * RPT)   // 512
#define CB_CHUNK   128         // codes staged in smem per chunk
#define SUB        8           // codes per accumulator batch

typedef unsigned long long u64;

__device__ __forceinline__ void fma2(u64 &d, u64 a, u64 b) {
    asm("fma.rn.f32x2 %0, %1, %2, %0;" : "+l"(d) : "l"(a), "l"(b));
}
__device__ __forceinline__ void unpack2(u64 u, float &lo, float &hi) {
    asm("mov.b64 {%0, %1}, %2;" : "=f"(lo), "=f"(hi) : "l"(u));
}

__global__ void __launch_bounds__(BLOCK, 1)
vq_kernel(const float* __restrict__ inputs,
          const float* __restrict__ codebook,
          float* __restrict__ out,
          int n_rows)
{
    __shared__ u64   c_s[CB_CHUNK * KP];   // 32 KB: [code][kpair] as f32x2
    __shared__ float csq_s[CB_CHUNK];

    const int tid  = threadIdx.x;
    const int row0 = blockIdx.x * ROWS_PER_BLOCK + tid;   // rows: row0, row0+BLOCK

    // ---- load this thread's 2 input rows fully into registers ----
    u64 x[RPT][KP];
    float xsq[RPT];
    const ulonglong2* inu = (const ulonglong2*)inputs;
    #pragma unroll
    for (int r = 0; r < RPT; r++) {
        long long base = (long long)(row0 + r * BLOCK) * (N_DIM / 4);
        #pragma unroll
        for (int t = 0; t < 16; t++) {
            ulonglong2 v = inu[base + t];
            x[r][2 * t]     = v.x;
            x[r][2 * t + 1] = v.y;
        }
        // x_sq: round products then sequential add (mimic sum(x*x))
        float s = 0.0f;
        #pragma unroll
        for (int t = 0; t < KP; t++) {
            float a, b; unpack2(x[r][t], a, b);
            s = __fadd_rn(s, __fmul_rn(a, a));
            s = __fadd_rn(s, __fmul_rn(b, b));
        }
        xsq[r] = s;
    }

    float best[RPT];
    int   bidx[RPT];
    #pragma unroll
    for (int r = 0; r < RPT; r++) { best[r] = 3.4e38f; bidx[r] = 0; }

    const u64* cbu = (const u64*)codebook;

    for (int chunk = 0; chunk < NCODES / CB_CHUNK; chunk++) {
        // ---- stage 128 codes into smem (32KB) ----
        {
            const u64* src = cbu + (size_t)chunk * CB_CHUNK * KP;
            #pragma unroll
            for (int i = 0; i < (CB_CHUNK * KP) / BLOCK; i++)
                c_s[tid + i * BLOCK] = src[tid + i * BLOCK];
        }
        __syncthreads();
        // ---- c_sq for this chunk ----
        if (tid < CB_CHUNK) {
            float s = 0.0f;
            #pragma unroll
            for (int t = 0; t < KP; t++) {
                float a, b; unpack2(c_s[tid * KP + t], a, b);
                s = __fadd_rn(s, __fmul_rn(a, a));
                s = __fadd_rn(s, __fmul_rn(b, b));
            }
            csq_s[tid] = s;
        }
        __syncthreads();

        // ---- main compute: 16 sub-batches of 8 codes ----
        for (int sub = 0; sub < CB_CHUNK / SUB; sub++) {
            u64 acc[RPT][SUB];
            #pragma unroll
            for (int r = 0; r < RPT; r++)
                #pragma unroll
                for (int j = 0; j < SUB; j++) acc[r][j] = 0ULL;

            const u64* cs = &c_s[(sub * SUB) * KP];
            #pragma unroll
            for (int kp = 0; kp < KP; kp++) {
                u64 cc[SUB];
                #pragma unroll
                for (int j = 0; j < SUB; j++) cc[j] = cs[j * KP + kp]; // broadcast
                #pragma unroll
                for (int r = 0; r < RPT; r++)
                    #pragma unroll
                    for (int j = 0; j < SUB; j++)
                        fma2(acc[r][j], x[r][kp], cc[j]);
            }

            const int code0 = chunk * CB_CHUNK + sub * SUB;
            #pragma unroll
            for (int r = 0; r < RPT; r++) {
                #pragma unroll
                for (int j = 0; j < SUB; j++) {
                    float lo, hi; unpack2(acc[r][j], lo, hi);
                    float dot = __fadd_rn(lo, hi);
                    // mimic reference: (x_sq - 2*xc) + c_sq, separate roundings
                    float m = __fmul_rn(2.0f, dot);
                    float t = __fsub_rn(xsq[r], m);
                    float d = __fadd_rn(t, csq_s[sub * SUB + j]);
                    if (d < best[r]) { best[r] = d; bidx[r] = code0 + j; }
                }
            }
        }
        __syncthreads();
    }

    // ---- gather winning codebook rows ----
    const float4* cb4  = (const float4*)codebook;
    float4*       out4 = (float4*)out;
    #pragma unroll
    for (int r = 0; r < RPT; r++) {
        long long row = row0 + r * BLOCK;
        const float4* src = cb4 + (size_t)bidx[r] * (N_DIM / 4);
        float4* dst = out4 + row * (N_DIM / 4);
        #pragma unroll
        for (int t = 0; t < N_DIM / 4; t++) dst[t] = src[t];
    }
}

extern "C" void kernel_launch(void* const* d_in, const int* in_sizes, int n_in,
                              void* d_out, int out_size)
{
    const float* inputs   = (const float*)d_in[0];
    const float* codebook = (const float*)d_in[1];
    float* out = (float*)d_out;
    int n_rows = in_sizes[0] / N_DIM;      // 262144
    int grid = n_rows / ROWS_PER_BLOCK;    // 512
    vq_kernel<<<grid, BLOCK>>>(inputs, codebook, out, n_rows);
}

// round 2
// speedup vs baseline: 1.0004x; 1.0004x over previous
#include <cuda_runtime.h>
#include <cstdint>

// VectorQuantizer: N=262144 inputs [N,64] f32, codebook [1024,64] f32.
// dist = x_sq - 2*x.c + c_sq ; out[row] = codebook[argmin(dist)].
// Strategy (round 0): fp32-exact distances using packed fma.rn.f32x2 (FFMA2).
//   - 2 rows per thread held fully in registers (64 f32x2 pairs)
//   - codebook staged in smem in 128-code chunks, warp-uniform broadcast LDS
//   - 8-code accumulator sub-batches -> 16 FFMA2 per 8 LDS per k-pair
//   - strict < argmin with ascending code order (matches argmin first-index ties)

#define N_DIM      64
#define KP         32          // k-pairs (f32x2)
#define NCODES     1024
#define BLOCK      256
#define RPT        2           // rows per thread
#define ROWS_PER_BLOCK (BLOCK * RPT)   // 512
#define CB_CHUNK   128         // codes staged in smem per chunk
#define SUB        8           // codes per accumulator batch

typedef unsigned long long u64;

__device__ __forceinline__ void fma2(u64 &d, u64 a, u64 b) {
    asm("fma.rn.f32x2 %0, %1, %2, %0;" : "+l"(d) : "l"(a), "l"(b));
}
__device__ __forceinline__ void unpack2(u64 u, float &lo, float &hi) {
    asm("mov.b64 {%0, %1}, %2;" : "=f"(lo), "=f"(hi) : "l"(u));
}

__global__ void __launch_bounds__(BLOCK, 1)
vq_kernel(const float* __restrict__ inputs,
          const float* __restrict__ codebook,
          float* __restrict__ out,
          int n_rows)
{
    __shared__ u64   c_s[CB_CHUNK * KP];   // 32 KB: [code][kpair] as f32x2
    __shared__ float csq_s[CB_CHUNK];

    const int tid  = threadIdx.x;
    const int row0 = blockIdx.x * ROWS_PER_BLOCK + tid;   // rows: row0, row0+BLOCK

    // ---- load this thread's 2 input rows fully into registers ----
    u64 x[RPT][KP];
    float xsq[RPT];
    const ulonglong2* inu = (const ulonglong2*)inputs;
    #pragma unroll
    for (int r = 0; r < RPT; r++) {
        long long base = (long long)(row0 + r * BLOCK) * (N_DIM / 4);
        #pragma unroll
        for (int t = 0; t < 16; t++) {
            ulonglong2 v = inu[base + t];
            x[r][2 * t]     = v.x;
            x[r][2 * t + 1] = v.y;
        }
        // x_sq: round products then sequential add (mimic sum(x*x))
        float s = 0.0f;
        #pragma unroll
        for (int t = 0; t < KP; t++) {
            float a, b; unpack2(x[r][t], a, b);
            s = __fadd_rn(s, __fmul_rn(a, a));
            s = __fadd_rn(s, __fmul_rn(b, b));
        }
        xsq[r] = s;
    }

    float best[RPT];
    int   bidx[RPT];
    #pragma unroll
    for (int r = 0; r < RPT; r++) { best[r] = 3.4e38f; bidx[r] = 0; }

    const u64* cbu = (const u64*)codebook;

    for (int chunk = 0; chunk < NCODES / CB_CHUNK; chunk++) {
        // ---- stage 128 codes into smem (32KB) ----
        {
            const u64* src = cbu + (size_t)chunk * CB_CHUNK * KP;
            #pragma unroll
            for (int i = 0; i < (CB_CHUNK * KP) / BLOCK; i++)
                c_s[tid + i * BLOCK] = src[tid + i * BLOCK];
        }
        __syncthreads();
        // ---- c_sq for this chunk ----
        if (tid < CB_CHUNK) {
            float s = 0.0f;
            #pragma unroll
            for (int t = 0; t < KP; t++) {
                float a, b; unpack2(c_s[tid * KP + t], a, b);
                s = __fadd_rn(s, __fmul_rn(a, a));
                s = __fadd_rn(s, __fmul_rn(b, b));
            }
            csq_s[tid] = s;
        }
        __syncthreads();

        // ---- main compute: 16 sub-batches of 8 codes ----
        for (int sub = 0; sub < CB_CHUNK / SUB; sub++) {
            u64 acc[RPT][SUB];
            #pragma unroll
            for (int r = 0; r < RPT; r++)
                #pragma unroll
                for (int j = 0; j < SUB; j++) acc[r][j] = 0ULL;

            const u64* cs = &c_s[(sub * SUB) * KP];
            #pragma unroll
            for (int kp = 0; kp < KP; kp++) {
                u64 cc[SUB];
                #pragma unroll
                for (int j = 0; j < SUB; j++) cc[j] = cs[j * KP + kp]; // broadcast
                #pragma unroll
                for (int r = 0; r < RPT; r++)
                    #pragma unroll
                    for (int j = 0; j < SUB; j++)
                        fma2(acc[r][j], x[r][kp], cc[j]);
            }

            const int code0 = chunk * CB_CHUNK + sub * SUB;
            #pragma unroll
            for (int r = 0; r < RPT; r++) {
                #pragma unroll
                for (int j = 0; j < SUB; j++) {
                    float lo, hi; unpack2(acc[r][j], lo, hi);
                    float dot = __fadd_rn(lo, hi);
                    // mimic reference: (x_sq - 2*xc) + c_sq, separate roundings
                    float m = __fmul_rn(2.0f, dot);
                    float t = __fsub_rn(xsq[r], m);
                    float d = __fadd_rn(t, csq_s[sub * SUB + j]);
                    if (d < best[r]) { best[r] = d; bidx[r] = code0 + j; }
                }
            }
        }
        __syncthreads();
    }

    // ---- gather winning codebook rows ----
    const float4* cb4  = (const float4*)codebook;
    float4*       out4 = (float4*)out;
    #pragma unroll
    for (int r = 0; r < RPT; r++) {
        long long row = row0 + r * BLOCK;
        const float4* src = cb4 + (size_t)bidx[r] * (N_DIM / 4);
        float4* dst = out4 + row * (N_DIM / 4);
        #pragma unroll
        for (int t = 0; t < N_DIM / 4; t++) dst[t] = src[t];
    }
}

extern "C" void kernel_launch(void* const* d_in, const int* in_sizes, int n_in,
                              void* d_out, int out_size)
{
    const float* inputs   = (const float*)d_in[0];
    const float* codebook = (const float*)d_in[1];
    float* out = (float*)d_out;
    int n_rows = in_sizes[0] / N_DIM;      // 262144
    int grid = n_rows / ROWS_PER_BLOCK;    // 512
    vq_kernel<<<grid, BLOCK>>>(inputs, codebook, out, n_rows);
}

// round 4
// speedup vs baseline: 1.3353x; 1.3348x over previous
#include <cuda_runtime.h>
#include <cuda_bf16.h>
#include <cstdint>

typedef unsigned long long u64;
typedef unsigned int u32;

#define NROWS    262144
#define NCODES   1024
#define NDIM     64
#define MROWS    256              // rows per screen CTA
#define NCHUNK   128              // codes per chunk
#define NCHUNKS  8
#define CHUNK_BYTES 33280         // 32KB frags + 512B csqh
#define CHUNK_U64   4160
#define SMEM_DYN (2 * CHUNK_BYTES)
#define MARGIN_S 0.02f            // score-gap margin (distance gap 0.04)

// ---- device globals (no allocs allowed) ----
__device__ u32   d_best[NROWS];
__device__ int   d_flag[NROWS];
__device__ int   d_nflag;
__device__ u64   d_cb_blob[NCHUNKS * CHUNK_U64];  // fragment-ordered bf16 codebook + csqh
__device__ float d_csq[NCODES];                    // exact, round-0 rounding order

// ---------------- helpers ----------------
__device__ __forceinline__ u32 smem_u32(const void* p) {
    u32 a; asm("{ .reg .u64 t; cvta.to.shared.u64 t, %1; cvt.u32.u64 %0, t; }" : "=r"(a) : "l"(p));
    return a;
}
__device__ __forceinline__ void fma2(u64 &d, u64 a, u64 b) {
    asm("fma.rn.f32x2 %0, %1, %2, %0;" : "+l"(d) : "l"(a), "l"(b));
}
__device__ __forceinline__ void unpack2(u64 u, float &lo, float &hi) {
    asm("mov.b64 {%0, %1}, %2;" : "=f"(lo), "=f"(hi) : "l"(u));
}
__device__ __forceinline__ void split2(float a0, float a1, u32& hi, u32& lo) {
    __nv_bfloat16 h0 = __float2bfloat16(a0), h1 = __float2bfloat16(a1);
    __nv_bfloat16 l0 = __float2bfloat16(a0 - __bfloat162float(h0));
    __nv_bfloat16 l1 = __float2bfloat16(a1 - __bfloat162float(h1));
    hi = (u32)*(unsigned short*)&h0 | ((u32)*(unsigned short*)&h1 << 16);
    lo = (u32)*(unsigned short*)&l0 | ((u32)*(unsigned short*)&l1 << 16);
}
__device__ __forceinline__ void mma16816(float* c, const u32* a, u32 b0, u32 b1) {
    asm volatile("mma.sync.aligned.m16n8k16.row.col.f32.bf16.bf16.f32 "
        "{%0,%1,%2,%3}, {%4,%5,%6,%7}, {%8,%9}, {%0,%1,%2,%3};"
        : "+f"(c[0]), "+f"(c[1]), "+f"(c[2]), "+f"(c[3])
        : "r"(a[0]), "r"(a[1]), "r"(a[2]), "r"(a[3]), "r"(b0), "r"(b1));
}
__device__ __forceinline__ void lds64(u32 addr, u32& x, u32& y) {
    asm volatile("ld.shared.v2.u32 {%0,%1}, [%2];" : "=r"(x), "=r"(y) : "r"(addr));
}
__device__ __forceinline__ void ldsf2(u32 addr, float& x, float& y) {
    asm volatile("ld.shared.v2.f32 {%0,%1}, [%2];" : "=f"(x), "=f"(y) : "r"(addr));
}
__device__ __forceinline__ void cp16(u32 dst, const void* src) {
    asm volatile("cp.async.cg.shared.global [%0], [%1], 16;" :: "r"(dst), "l"(src) : "memory");
}
__device__ __forceinline__ void cp_commit() { asm volatile("cp.async.commit_group;" ::: "memory"); }
__device__ __forceinline__ void upd(float s, int code, float& b1, float& b2, int& i1) {
    if (s > b1) { b2 = b1; b1 = s; i1 = code; } else b2 = fmaxf(b2, s);
}

// ---------------- K0a: exact csq (+ csqh into blob), reset flag count ----------------
__global__ void vq_csq(const float* __restrict__ cb) {
    int code = blockIdx.x * blockDim.x + threadIdx.x;
    if (code == 0) d_nflag = 0;
    if (code >= NCODES) return;
    const float4* c4 = (const float4*)(cb + (size_t)code * NDIM);
    float s = 0.f;
    #pragma unroll
    for (int t = 0; t < 16; t++) {
        float4 v = c4[t];
        s = __fadd_rn(s, __fmul_rn(v.x, v.x));
        s = __fadd_rn(s, __fmul_rn(v.y, v.y));
        s = __fadd_rn(s, __fmul_rn(v.z, v.z));
        s = __fadd_rn(s, __fmul_rn(v.w, v.w));
    }
    d_csq[code] = s;
    int chunk = code >> 7, ci = code & 127;
    ((float*)d_cb_blob)[chunk * (CHUNK_BYTES / 4) + 8192 + ci] = -0.5f * s;
}

// ---------------- K0b: codebook -> mma B fragments (hi/lo split) ----------------
// blob[chunk] layout: u64[(ksl*16 + nt)*32 + lane] ; ksl 0..3 = hi(ks), 4..7 = lo(ks)
// B frag (m16n8k16 col-major B): reg0 = B[k0+{0,1}][n], reg1 = B[k0+8+{0,1}][n]
//   with n = lane>>2, k0 = (lane&3)*2, k base = ks*16.
__global__ void vq_frag(const float* __restrict__ cb) {
    int g = blockIdx.x * blockDim.x + threadIdx.x;   // 32768 threads
    int lane = g & 31, nt = (g >> 5) & 15, ksl = (g >> 9) & 7, chunk = g >> 12;
    int ks = ksl & 3;
    bool want_lo = (ksl >= 4);
    int code = chunk * NCHUNK + nt * 8 + (lane >> 2);
    int k0 = ks * 16 + (lane & 3) * 2;
    const float* row = cb + (size_t)code * NDIM;
    float2 p0 = *(const float2*)(row + k0);
    float2 p1 = *(const float2*)(row + k0 + 8);
    u32 h0, l0, h1, l1;
    split2(p0.x, p0.y, h0, l0);
    split2(p1.x, p1.y, h1, l1);
    u32 r0 = want_lo ? l0 : h0;
    u32 r1 = want_lo ? l1 : h1;
    d_cb_blob[(size_t)chunk * CHUNK_U64 + ((ksl * 16 + nt) * 32 + lane)] =
        (u64)r0 | ((u64)r1 << 32);
}

// ---------------- K1: HMMA screen ----------------
__global__ void __launch_bounds__(256, 1)
vq_screen(const float* __restrict__ inputs) {
    extern __shared__ char smem[];
    const u32 sbase = smem_u32(smem);
    const int tid = threadIdx.x, wid = tid >> 5, lane = tid & 31;
    const int q = lane & 3, rg = lane >> 2;
    const int ctaRow0 = blockIdx.x * MROWS;

    // ---- prefetch chunk 0 ----
    {
        const char* src = (const char*)d_cb_blob;
        for (int j = tid; j < CHUNK_BYTES / 16; j += 256)
            cp16(sbase + (u32)j * 16u, src + (size_t)j * 16);
        cp_commit();
    }

    // ---- build A fragments in registers (hi/lo split), 2 tiles of 16 rows ----
    u32 Ahi[2][4][4], Alo[2][4][4];
    #pragma unroll
    for (int t = 0; t < 2; t++) {
        const float* pA = inputs + (size_t)(ctaRow0 + wid * 32 + t * 16 + rg) * NDIM;
        const float* pB = pA + 8 * NDIM;
        #pragma unroll
        for (int ks = 0; ks < 4; ks++) {
            int k0 = ks * 16 + q * 2;
            float2 a0 = *(const float2*)(pA + k0);
            float2 a1 = *(const float2*)(pB + k0);
            float2 a2 = *(const float2*)(pA + k0 + 8);
            float2 a3 = *(const float2*)(pB + k0 + 8);
            split2(a0.x, a0.y, Ahi[t][ks][0], Alo[t][ks][0]);
            split2(a1.x, a1.y, Ahi[t][ks][1], Alo[t][ks][1]);
            split2(a2.x, a2.y, Ahi[t][ks][2], Alo[t][ks][2]);
            split2(a3.x, a3.y, Ahi[t][ks][3], Alo[t][ks][3]);
        }
    }

    float b1[4], b2[4];
    int   i1[4];
    #pragma unroll
    for (int s = 0; s < 4; s++) { b1[s] = -3.4e38f; b2[s] = -3.4e38f; i1[s] = 0; }

    for (int c = 0; c < NCHUNKS; c++) {
        // prefetch next chunk into other buffer
        if (c + 1 < NCHUNKS) {
            u32 dst = sbase + (u32)((c + 1) & 1) * CHUNK_BYTES;
            const char* src = (const char*)d_cb_blob + (size_t)(c + 1) * CHUNK_BYTES;
            for (int j = tid; j < CHUNK_BYTES / 16; j += 256)
                cp16(dst + (u32)j * 16u, src + (size_t)j * 16);
            cp_commit();
            asm volatile("cp.async.wait_group 1;" ::: "memory");
        } else {
            asm volatile("cp.async.wait_group 0;" ::: "memory");
        }
        __syncthreads();

        const u32 bbase = sbase + (u32)(c & 1) * CHUNK_BYTES;
        const int cbase = c * NCHUNK;

        #pragma unroll 2
        for (int np = 0; np < 8; np++) {
            const int nt0 = 2 * np, nt1 = nt0 + 1;
            float C00[4] = {0,0,0,0}, C01[4] = {0,0,0,0};
            float C10[4] = {0,0,0,0}, C11[4] = {0,0,0,0};
            u32 x0, x1, y0, y1;
            #pragma unroll
            for (int ks = 0; ks < 4; ks++) {      // B = hi_c
                lds64(bbase + (u32)(((ks * 16 + nt0) * 32 + lane) * 8), x0, x1);
                lds64(bbase + (u32)(((ks * 16 + nt1) * 32 + lane) * 8), y0, y1);
                mma16816(C00, Ahi[0][ks], x0, x1);
                mma16816(C01, Ahi[0][ks], y0, y1);
                mma16816(C10, Ahi[1][ks], x0, x1);
                mma16816(C11, Ahi[1][ks], y0, y1);
                mma16816(C00, Alo[0][ks], x0, x1);
                mma16816(C01, Alo[0][ks], y0, y1);
                mma16816(C10, Alo[1][ks], x0, x1);
                mma16816(C11, Alo[1][ks], y0, y1);
            }
            #pragma unroll
            for (int ks = 0; ks < 4; ks++) {      // B = lo_c, A = hi_x
                lds64(bbase + (u32)((((4 + ks) * 16 + nt0) * 32 + lane) * 8), x0, x1);
                lds64(bbase + (u32)((((4 + ks) * 16 + nt1) * 32 + lane) * 8), y0, y1);
                mma16816(C00, Ahi[0][ks], x0, x1);
                mma16816(C01, Ahi[0][ks], y0, y1);
                mma16816(C10, Ahi[1][ks], x0, x1);
                mma16816(C11, Ahi[1][ks], y0, y1);
            }
            // epilogue: scores = C + csqh ; per-thread top-2
            float q00, q01, q10, q11;
            ldsf2(bbase + 32768u + (u32)((nt0 * 8 + q * 2) * 4), q00, q01);
            ldsf2(bbase + 32768u + (u32)((nt1 * 8 + q * 2) * 4), q10, q11);
            const int n00 = cbase + nt0 * 8 + q * 2;
            const int n10 = cbase + nt1 * 8 + q * 2;
            upd(C00[0] + q00, n00,     b1[0], b2[0], i1[0]);
            upd(C00[1] + q01, n00 + 1, b1[0], b2[0], i1[0]);
            upd(C00[2] + q00, n00,     b1[1], b2[1], i1[1]);
            upd(C00[3] + q01, n00 + 1, b1[1], b2[1], i1[1]);
            upd(C01[0] + q10, n10,     b1[0], b2[0], i1[0]);
            upd(C01[1] + q11, n10 + 1, b1[0], b2[0], i1[0]);
            upd(C01[2] + q10, n10,     b1[1], b2[1], i1[1]);
            upd(C01[3] + q11, n10 + 1, b1[1], b2[1], i1[1]);
            upd(C10[0] + q00, n00,     b1[2], b2[2], i1[2]);
            upd(C10[1] + q01, n00 + 1, b1[2], b2[2], i1[2]);
            upd(C10[2] + q00, n00,     b1[3], b2[3], i1[3]);
            upd(C10[3] + q01, n00 + 1, b1[3], b2[3], i1[3]);
            upd(C11[0] + q10, n10,     b1[2], b2[2], i1[2]);
            upd(C11[1] + q11, n10 + 1, b1[2], b2[2], i1[2]);
            upd(C11[2] + q10, n10,     b1[3], b2[3], i1[3]);
            upd(C11[3] + q11, n10 + 1, b1[3], b2[3], i1[3]);
        }
        __syncthreads();
    }

    // ---- merge top-2 across the 4 lanes sharing each row ----
    #pragma unroll
    for (int o = 1; o <= 2; o <<= 1) {
        #pragma unroll
        for (int s = 0; s < 4; s++) {
            float o1 = __shfl_xor_sync(0xffffffffu, b1[s], o);
            float o2 = __shfl_xor_sync(0xffffffffu, b2[s], o);
            int   oi = __shfl_xor_sync(0xffffffffu, i1[s], o);
            float mn = fminf(b1[s], o1);
            b2[s] = fmaxf(fmaxf(b2[s], o2), mn);
            if (o1 > b1[s]) { b1[s] = o1; i1[s] = oi; }
        }
    }

    if (q == 0) {
        #pragma unroll
        for (int s = 0; s < 4; s++) {
            int t = s >> 1, h = s & 1;
            int row = ctaRow0 + wid * 32 + t * 16 + h * 8 + rg;
            d_best[row] = (u32)i1[s];
            if (b1[s] - b2[s] < MARGIN_S) {
                int p = atomicAdd(&d_nflag, 1);
                d_flag[p] = row;
            }
        }
    }
}

// ---------------- K2: exact refine of flagged rows (round-0 arithmetic) ----------------
__global__ void vq_refine(const float* __restrict__ inputs, const float* __restrict__ cb) {
    const int n    = d_nflag;
    const int nw   = (gridDim.x * blockDim.x) >> 5;
    const int w    = (blockIdx.x * blockDim.x + threadIdx.x) >> 5;
    const int lane = threadIdx.x & 31;
    for (int it = w; it < n; it += nw) {
        int row = d_flag[it];
        const u64* xp = (const u64*)(inputs + (size_t)row * NDIM);
        u64 xr[32];
        #pragma unroll
        for (int t = 0; t < 32; t++) xr[t] = xp[t];
        float xsq = 0.f;
        #pragma unroll
        for (int t = 0; t < 32; t++) {
            float a, b; unpack2(xr[t], a, b);
            xsq = __fadd_rn(xsq, __fmul_rn(a, a));
            xsq = __fadd_rn(xsq, __fmul_rn(b, b));
        }
        float best = 3.4e38f; int bi = 0;
        for (int cbase2 = 0; cbase2 < NCODES; cbase2 += 32) {
            int c = cbase2 + lane;
            u64 acc = 0ULL;
            const u64* cp = (const u64*)(cb + (size_t)c * NDIM);
            #pragma unroll
            for (int t = 0; t < 32; t++) fma2(acc, xr[t], cp[t]);
            float lo, hi; unpack2(acc, lo, hi);
            float dot = __fadd_rn(lo, hi);
            float d = __fadd_rn(__fsub_rn(xsq, __fmul_rn(2.0f, dot)), d_csq[c]);
            if (d < best) { best = d; bi = c; }
        }
        #pragma unroll
        for (int o = 16; o; o >>= 1) {
            float ob = __shfl_xor_sync(0xffffffffu, best, o);
            int   oi = __shfl_xor_sync(0xffffffffu, bi, o);
            if (ob < best || (ob == best && oi < bi)) { best = ob; bi = oi; }
        }
        if (lane == 0) d_best[row] = (u32)bi;
    }
}

// ---------------- K3: gather ----------------
__global__ void vq_gather(const float* __restrict__ cb, float* __restrict__ out) {
    int t = blockIdx.x * blockDim.x + threadIdx.x;
    int row = t >> 2, part = t & 3;
    u32 bi = d_best[row];
    const float4* s = (const float4*)cb + (size_t)bi * 16 + part * 4;
    float4* o = (float4*)out + (size_t)row * 16 + part * 4;
    o[0] = s[0]; o[1] = s[1]; o[2] = s[2]; o[3] = s[3];
}

// ---------------- host launch ----------------
extern "C" void kernel_launch(void* const* d_in, const int* in_sizes, int n_in,
                              void* d_out, int out_size)
{
    const float* inputs   = (const float*)d_in[0];
    const float* codebook = (const float*)d_in[1];
    float* out = (float*)d_out;

    cudaFuncSetAttribute(vq_screen, cudaFuncAttributeMaxDynamicSharedMemorySize, SMEM_DYN);

    vq_csq   <<<NCODES / 256, 256>>>(codebook);
    vq_frag  <<<128, 256>>>(codebook);
    vq_screen<<<NROWS / MROWS, 256, SMEM_DYN>>>(inputs);
    vq_refine<<<256, 256>>>(inputs, codebook);
    vq_gather<<<NROWS * 4 / 256, 256>>>(codebook, out);
}

// round 5
// speedup vs baseline: 2.9365x; 2.1990x over previous
#include <cuda_runtime.h>
#include <cuda_bf16.h>
#include <cstdint>

typedef unsigned long long u64;
typedef unsigned int u32;

#define NROWS    262144
#define NCODES   1024
#define NDIM     64
#define MROWS    256              // rows per screen CTA
#define NCHUNK   64               // codes per chunk
#define NCHUNKS  16
#define CHUNK_BYTES 16896         // 16KB frags + 256B csqh + pad
#define CHUNK_U64   2112
#define SMEM_DYN (2 * CHUNK_BYTES)
#define MARGIN_S 0.006f           // score-gap margin (distance gap 0.012)

// ---- device globals (no allocs allowed) ----
__device__ u64   d_bestkey[NROWS];               // (distbits<<32)|code ; unflagged: code only
__device__ int   d_flag[NROWS];
__device__ int   d_nflag;
__device__ u64   d_cb_blob[NCHUNKS * CHUNK_U64]; // fragment-ordered bf16 codebook + csqh
__device__ float d_csq[NCODES];
__device__ float d_cbT[NDIM * NCODES];           // transposed codebook for refine

// ---------------- helpers ----------------
__device__ __forceinline__ u32 smem_u32(const void* p) {
    u32 a; asm("{ .reg .u64 t; cvta.to.shared.u64 t, %1; cvt.u32.u64 %0, t; }" : "=r"(a) : "l"(p));
    return a;
}
__device__ __forceinline__ void split2(float a0, float a1, u32& hi, u32& lo) {
    __nv_bfloat16 h0 = __float2bfloat16(a0), h1 = __float2bfloat16(a1);
    __nv_bfloat16 l0 = __float2bfloat16(a0 - __bfloat162float(h0));
    __nv_bfloat16 l1 = __float2bfloat16(a1 - __bfloat162float(h1));
    hi = (u32)*(unsigned short*)&h0 | ((u32)*(unsigned short*)&h1 << 16);
    lo = (u32)*(unsigned short*)&l0 | ((u32)*(unsigned short*)&l1 << 16);
}
__device__ __forceinline__ void mma16816(float* c, const u32* a, u32 b0, u32 b1) {
    asm volatile("mma.sync.aligned.m16n8k16.row.col.f32.bf16.bf16.f32 "
        "{%0,%1,%2,%3}, {%4,%5,%6,%7}, {%8,%9}, {%0,%1,%2,%3};"
        : "+f"(c[0]), "+f"(c[1]), "+f"(c[2]), "+f"(c[3])
        : "r"(a[0]), "r"(a[1]), "r"(a[2]), "r"(a[3]), "r"(b0), "r"(b1));
}
__device__ __forceinline__ void lds64(u32 addr, u32& x, u32& y) {
    asm volatile("ld.shared.v2.u32 {%0,%1}, [%2];" : "=r"(x), "=r"(y) : "r"(addr));
}
__device__ __forceinline__ void ldsf2(u32 addr, float& x, float& y) {
    asm volatile("ld.shared.v2.f32 {%0,%1}, [%2];" : "=f"(x), "=f"(y) : "r"(addr));
}
__device__ __forceinline__ void cp16(u32 dst, const void* src) {
    asm volatile("cp.async.cg.shared.global [%0], [%1], 16;" :: "r"(dst), "l"(src) : "memory");
}
__device__ __forceinline__ void cp_commit() { asm volatile("cp.async.commit_group;" ::: "memory"); }
__device__ __forceinline__ void upd(float s, int code, float& b1, float& b2, int& i1) {
    if (s > b1) { b2 = b1; b1 = s; i1 = code; } else b2 = fmaxf(b2, s);
}

// ---------------- K0a: exact csq + csqh into blob + cbT, reset flag count ----------------
__global__ void vq_csq(const float* __restrict__ cb) {
    int code = blockIdx.x * blockDim.x + threadIdx.x;
    if (code == 0) d_nflag = 0;
    if (code >= NCODES) return;
    const float4* c4 = (const float4*)(cb + (size_t)code * NDIM);
    float s = 0.f;
    #pragma unroll
    for (int t = 0; t < 16; t++) {
        float4 v = c4[t];
        s = __fadd_rn(s, __fmul_rn(v.x, v.x));
        s = __fadd_rn(s, __fmul_rn(v.y, v.y));
        s = __fadd_rn(s, __fmul_rn(v.z, v.z));
        s = __fadd_rn(s, __fmul_rn(v.w, v.w));
        d_cbT[(4*t+0) * NCODES + code] = v.x;
        d_cbT[(4*t+1) * NCODES + code] = v.y;
        d_cbT[(4*t+2) * NCODES + code] = v.z;
        d_cbT[(4*t+3) * NCODES + code] = v.w;
    }
    d_csq[code] = s;
    int chunk = code >> 6, ci = code & 63;
    ((float*)d_cb_blob)[chunk * (CHUNK_BYTES / 4) + 4096 + ci] = -0.5f * s;
}

// ---------------- K0b: codebook -> mma B fragments (hi/lo split) ----------------
// blob[chunk] layout: u64[(ksl*8 + nt)*32 + lane]; ksl 0..3 = hi(ks), 4..7 = lo(ks)
__global__ void vq_frag(const float* __restrict__ cb) {
    int g = blockIdx.x * blockDim.x + threadIdx.x;   // 32768 threads
    int lane = g & 31, nt = (g >> 5) & 7, ksl = (g >> 8) & 7, chunk = g >> 11;
    int ks = ksl & 3;
    bool want_lo = (ksl >= 4);
    int code = chunk * NCHUNK + nt * 8 + (lane >> 2);
    int k0 = ks * 16 + (lane & 3) * 2;
    const float* row = cb + (size_t)code * NDIM;
    float2 p0 = *(const float2*)(row + k0);
    float2 p1 = *(const float2*)(row + k0 + 8);
    u32 h0, l0, h1, l1;
    split2(p0.x, p0.y, h0, l0);
    split2(p1.x, p1.y, h1, l1);
    u32 r0 = want_lo ? l0 : h0;
    u32 r1 = want_lo ? l1 : h1;
    d_cb_blob[(size_t)chunk * CHUNK_U64 + ((ksl * 8 + nt) * 32 + lane)] =
        (u64)r0 | ((u64)r1 << 32);
}

// ---------------- K1: HMMA screen ----------------
__global__ void __launch_bounds__(256, 2)
vq_screen(const float* __restrict__ inputs) {
    extern __shared__ char smem[];
    const u32 sbase = smem_u32(smem);
    const int tid = threadIdx.x, wid = tid >> 5, lane = tid & 31;
    const int q = lane & 3, rg = lane >> 2;
    const int ctaRow0 = blockIdx.x * MROWS;

    // prefetch chunk 0
    {
        const char* src = (const char*)d_cb_blob;
        for (int j = tid; j < CHUNK_BYTES / 16; j += 256)
            cp16(sbase + (u32)j * 16u, src + (size_t)j * 16);
        cp_commit();
    }

    // build A fragments in registers (hi/lo split), 2 tiles of 16 rows
    u32 Ahi[2][4][4], Alo[2][4][4];
    #pragma unroll
    for (int t = 0; t < 2; t++) {
        const float* pA = inputs + (size_t)(ctaRow0 + wid * 32 + t * 16 + rg) * NDIM;
        const float* pB = pA + 8 * NDIM;
        #pragma unroll
        for (int ks = 0; ks < 4; ks++) {
            int k0 = ks * 16 + q * 2;
            float2 a0 = *(const float2*)(pA + k0);
            float2 a1 = *(const float2*)(pB + k0);
            float2 a2 = *(const float2*)(pA + k0 + 8);
            float2 a3 = *(const float2*)(pB + k0 + 8);
            split2(a0.x, a0.y, Ahi[t][ks][0], Alo[t][ks][0]);
            split2(a1.x, a1.y, Ahi[t][ks][1], Alo[t][ks][1]);
            split2(a2.x, a2.y, Ahi[t][ks][2], Alo[t][ks][2]);
            split2(a3.x, a3.y, Ahi[t][ks][3], Alo[t][ks][3]);
        }
    }

    float b1[4], b2[4];
    int   i1[4];
    #pragma unroll
    for (int s = 0; s < 4; s++) { b1[s] = -3.4e38f; b2[s] = -3.4e38f; i1[s] = 0; }

    for (int c = 0; c < NCHUNKS; c++) {
        if (c + 1 < NCHUNKS) {
            u32 dst = sbase + (u32)((c + 1) & 1) * CHUNK_BYTES;
            const char* src = (const char*)d_cb_blob + (size_t)(c + 1) * CHUNK_BYTES;
            for (int j = tid; j < CHUNK_BYTES / 16; j += 256)
                cp16(dst + (u32)j * 16u, src + (size_t)j * 16);
            cp_commit();
            asm volatile("cp.async.wait_group 1;" ::: "memory");
        } else {
            asm volatile("cp.async.wait_group 0;" ::: "memory");
        }
        __syncthreads();

        const u32 bbase = sbase + (u32)(c & 1) * CHUNK_BYTES;
        const int cbase = c * NCHUNK;

        #pragma unroll 2
        for (int np = 0; np < 4; np++) {
            const int nt0 = 2 * np, nt1 = nt0 + 1;
            float C00[4] = {0,0,0,0}, C01[4] = {0,0,0,0};
            float C10[4] = {0,0,0,0}, C11[4] = {0,0,0,0};
            u32 x0, x1, y0, y1;
            #pragma unroll
            for (int ks = 0; ks < 4; ks++) {      // B = hi_c : A = hi_x and lo_x
                lds64(bbase + (u32)(((ks * 8 + nt0) * 32 + lane) * 8), x0, x1);
                lds64(bbase + (u32)(((ks * 8 + nt1) * 32 + lane) * 8), y0, y1);
                mma16816(C00, Ahi[0][ks], x0, x1);
                mma16816(C01, Ahi[0][ks], y0, y1);
                mma16816(C10, Ahi[1][ks], x0, x1);
                mma16816(C11, Ahi[1][ks], y0, y1);
                mma16816(C00, Alo[0][ks], x0, x1);
                mma16816(C01, Alo[0][ks], y0, y1);
                mma16816(C10, Alo[1][ks], x0, x1);
                mma16816(C11, Alo[1][ks], y0, y1);
            }
            #pragma unroll
            for (int ks = 0; ks < 4; ks++) {      // B = lo_c : A = hi_x
                lds64(bbase + (u32)((((4 + ks) * 8 + nt0) * 32 + lane) * 8), x0, x1);
                lds64(bbase + (u32)((((4 + ks) * 8 + nt1) * 32 + lane) * 8), y0, y1);
                mma16816(C00, Ahi[0][ks], x0, x1);
                mma16816(C01, Ahi[0][ks], y0, y1);
                mma16816(C10, Ahi[1][ks], x0, x1);
                mma16816(C11, Ahi[1][ks], y0, y1);
            }
            // epilogue: scores = C + csqh ; per-thread top-2
            float q00, q01, q10, q11;
            ldsf2(bbase + 16384u + (u32)((nt0 * 8 + q * 2) * 4), q00, q01);
            ldsf2(bbase + 16384u + (u32)((nt1 * 8 + q * 2) * 4), q10, q11);
            const int n00 = cbase + nt0 * 8 + q * 2;
            const int n10 = cbase + nt1 * 8 + q * 2;
            upd(C00[0] + q00, n00,     b1[0], b2[0], i1[0]);
            upd(C00[1] + q01, n00 + 1, b1[0], b2[0], i1[0]);
            upd(C00[2] + q00, n00,     b1[1], b2[1], i1[1]);
            upd(C00[3] + q01, n00 + 1, b1[1], b2[1], i1[1]);
            upd(C01[0] + q10, n10,     b1[0], b2[0], i1[0]);
            upd(C01[1] + q11, n10 + 1, b1[0], b2[0], i1[0]);
            upd(C01[2] + q10, n10,     b1[1], b2[1], i1[1]);
            upd(C01[3] + q11, n10 + 1, b1[1], b2[1], i1[1]);
            upd(C10[0] + q00, n00,     b1[2], b2[2], i1[2]);
            upd(C10[1] + q01, n00 + 1, b1[2], b2[2], i1[2]);
            upd(C10[2] + q00, n00,     b1[3], b2[3], i1[3]);
            upd(C10[3] + q01, n00 + 1, b1[3], b2[3], i1[3]);
            upd(C11[0] + q10, n10,     b1[2], b2[2], i1[2]);
            upd(C11[1] + q11, n10 + 1, b1[2], b2[2], i1[2]);
            upd(C11[2] + q10, n10,     b1[3], b2[3], i1[3]);
            upd(C11[3] + q11, n10 + 1, b1[3], b2[3], i1[3]);
        }
        __syncthreads();
    }

    // merge top-2 across the 4 lanes sharing each row
    #pragma unroll
    for (int o = 1; o <= 2; o <<= 1) {
        #pragma unroll
        for (int s = 0; s < 4; s++) {
            float o1 = __shfl_xor_sync(0xffffffffu, b1[s], o);
            float o2 = __shfl_xor_sync(0xffffffffu, b2[s], o);
            int   oi = __shfl_xor_sync(0xffffffffu, i1[s], o);
            float mn = fminf(b1[s], o1);
            b2[s] = fmaxf(fmaxf(b2[s], o2), mn);
            if (o1 > b1[s]) { b1[s] = o1; i1[s] = oi; }
        }
    }

    if (q == 0) {
        #pragma unroll
        for (int s = 0; s < 4; s++) {
            int t = s >> 1, h = s & 1;
            int row = ctaRow0 + wid * 32 + t * 16 + h * 8 + rg;
            if (b1[s] - b2[s] < MARGIN_S) {
                d_bestkey[row] = ~0ULL;
                int p = atomicAdd(&d_nflag, 1);
                d_flag[p] = row;
            } else {
                d_bestkey[row] = (u64)(u32)i1[s];
            }
        }
    }
}

// ---------------- K2: exact refine of flagged rows, coalesced over cbT ----------------
__global__ void vq_refine(const float* __restrict__ inputs) {
    const int n     = d_nflag;
    const int nwarp = (gridDim.x * blockDim.x) >> 5;
    const int w     = (blockIdx.x * blockDim.x + threadIdx.x) >> 5;
    const int lane  = threadIdx.x & 31;
    const int nitems = n * 32;                 // 32 code-blocks of 32 per row
    for (int item = w; item < nitems; item += nwarp) {
        const int row = d_flag[item >> 5];
        const int c   = ((item & 31) << 5) + lane;
        const float* x = inputs + (size_t)row * NDIM;
        float acc = 0.f, xs = 0.f;
        #pragma unroll
        for (int d = 0; d < NDIM; d++) {
            float xv = __ldg(x + d);
            acc = __fmaf_rn(xv, d_cbT[d * NCODES + c], acc);
            xs  = __fmaf_rn(xv, xv, xs);
        }
        float dist = __fadd_rn(__fsub_rn(xs, __fmul_rn(2.0f, acc)), d_csq[c]);
        dist = fmaxf(dist, 0.0f);
        u64 key = ((u64)__float_as_uint(dist) << 32) | (u32)c;
        // warp-reduce min, then single atomic
        #pragma unroll
        for (int o = 16; o; o >>= 1) {
            u64 ok = __shfl_xor_sync(0xffffffffu, key, o);
            key = (ok < key) ? ok : key;
        }
        if (lane == 0) atomicMin(&d_bestkey[row], key);
    }
}

// ---------------- K3: gather ----------------
__global__ void vq_gather(const float* __restrict__ cb, float* __restrict__ out) {
    int t = blockIdx.x * blockDim.x + threadIdx.x;
    int row = t >> 2, part = t & 3;
    u32 bi = (u32)(d_bestkey[row] & 0xFFFFFFFFu);
    const float4* s = (const float4*)cb + (size_t)bi * 16 + part * 4;
    float4* o = (float4*)out + (size_t)row * 16 + part * 4;
    o[0] = s[0]; o[1] = s[1]; o[2] = s[2]; o[3] = s[3];
}

// ---------------- host launch ----------------
extern "C" void kernel_launch(void* const* d_in, const int* in_sizes, int n_in,
                              void* d_out, int out_size)
{
    const float* inputs   = (const float*)d_in[0];
    const float* codebook = (const float*)d_in[1];
    float* out = (float*)d_out;

    cudaFuncSetAttribute(vq_screen, cudaFuncAttributeMaxDynamicSharedMemorySize, SMEM_DYN);

    vq_csq   <<<NCODES / 256, 256>>>(codebook);
    vq_frag  <<<128, 256>>>(codebook);
    vq_screen<<<NROWS / MROWS, 256, SMEM_DYN>>>(inputs);
    vq_refine<<<256, 256>>>(inputs);
    vq_gather<<<NROWS * 4 / 256, 256>>>(codebook, out);
}

// round 6
// speedup vs baseline: 3.0211x; 1.0288x over previous
#include <cuda_runtime.h>
#include <cuda_fp16.h>
#include <cstdint>

typedef unsigned long long u64;
typedef unsigned int u32;

#define NROWS    262144
#define NCODES   1024
#define NDIM     64
#define MROWS    256              // rows per screen CTA
#define NCHUNK   64               // codes per chunk
#define NCHUNKS  16
#define CHUNK_BYTES 16896         // 16KB frags + 256B csqh + pad
#define CHUNK_U64   2112
#define SMEM_DYN (2 * CHUNK_BYTES)
#define MARGIN_S 0.002f           // score-gap margin (distance gap 0.004)

// ---- device globals (no allocs allowed) ----
__device__ u64   d_bestkey[NROWS];               // (distbits<<32)|code ; unflagged: code only
__device__ int   d_flag[NROWS];
__device__ int   d_nflag;
__device__ u64   d_cb_blob[NCHUNKS * CHUNK_U64]; // fragment-ordered fp16 codebook + csqh
__device__ float d_csq[NCODES];
__device__ float d_cbT[NDIM * NCODES];           // transposed codebook for refine

// ---------------- helpers ----------------
__device__ __forceinline__ u32 smem_u32(const void* p) {
    u32 a; asm("{ .reg .u64 t; cvta.to.shared.u64 t, %1; cvt.u32.u64 %0, t; }" : "=r"(a) : "l"(p));
    return a;
}
__device__ __forceinline__ void split2h(float a0, float a1, u32& hi, u32& lo) {
    __half h0 = __float2half_rn(a0), h1 = __float2half_rn(a1);
    __half l0 = __float2half_rn(a0 - __half2float(h0));
    __half l1 = __float2half_rn(a1 - __half2float(h1));
    hi = (u32)*(unsigned short*)&h0 | ((u32)*(unsigned short*)&h1 << 16);
    lo = (u32)*(unsigned short*)&l0 | ((u32)*(unsigned short*)&l1 << 16);
}
// f32-accumulate fp16 MMA (rt ~8)
__device__ __forceinline__ void mma_f32(float* c, const u32* a, u32 b0, u32 b1) {
    asm volatile("mma.sync.aligned.m16n8k16.row.col.f32.f16.f16.f32 "
        "{%0,%1,%2,%3}, {%4,%5,%6,%7}, {%8,%9}, {%0,%1,%2,%3};"
        : "+f"(c[0]), "+f"(c[1]), "+f"(c[2]), "+f"(c[3])
        : "r"(a[0]), "r"(a[1]), "r"(a[2]), "r"(a[3]), "r"(b0), "r"(b1));
}
// f16-accumulate fp16 MMA (rt ~4, used for small cross terms)
__device__ __forceinline__ void mma_f16(u32* c, const u32* a, u32 b0, u32 b1) {
    asm volatile("mma.sync.aligned.m16n8k16.row.col.f16.f16.f16.f16 "
        "{%0,%1}, {%2,%3,%4,%5}, {%6,%7}, {%0,%1};"
        : "+r"(c[0]), "+r"(c[1])
        : "r"(a[0]), "r"(a[1]), "r"(a[2]), "r"(a[3]), "r"(b0), "r"(b1));
}
__device__ __forceinline__ void lds64(u32 addr, u32& x, u32& y) {
    asm volatile("ld.shared.v2.u32 {%0,%1}, [%2];" : "=r"(x), "=r"(y) : "r"(addr));
}
__device__ __forceinline__ void ldsf2(u32 addr, float& x, float& y) {
    asm volatile("ld.shared.v2.f32 {%0,%1}, [%2];" : "=f"(x), "=f"(y) : "r"(addr));
}
__device__ __forceinline__ void cp16(u32 dst, const void* src) {
    asm volatile("cp.async.cg.shared.global [%0], [%1], 16;" :: "r"(dst), "l"(src) : "memory");
}
__device__ __forceinline__ void cp_commit() { asm volatile("cp.async.commit_group;" ::: "memory"); }
__device__ __forceinline__ void upd(float s, int code, float& b1, float& b2, int& i1) {
    if (s > b1) { b2 = b1; b1 = s; i1 = code; } else b2 = fmaxf(b2, s);
}
__device__ __forceinline__ void fma2(u64 &d, u64 a, u64 b) {
    asm("fma.rn.f32x2 %0, %1, %2, %0;" : "+l"(d) : "l"(a), "l"(b));
}

// ---------------- K0a: exact csq + csqh into blob + cbT, reset flag count ----------------
__global__ void vq_csq(const float* __restrict__ cb) {
    int code = blockIdx.x * blockDim.x + threadIdx.x;
    if (code == 0) d_nflag = 0;
    if (code >= NCODES) return;
    const float4* c4 = (const float4*)(cb + (size_t)code * NDIM);
    float s = 0.f;
    #pragma unroll
    for (int t = 0; t < 16; t++) {
        float4 v = c4[t];
        s = __fadd_rn(s, __fmul_rn(v.x, v.x));
        s = __fadd_rn(s, __fmul_rn(v.y, v.y));
        s = __fadd_rn(s, __fmul_rn(v.z, v.z));
        s = __fadd_rn(s, __fmul_rn(v.w, v.w));
        d_cbT[(4*t+0) * NCODES + code] = v.x;
        d_cbT[(4*t+1) * NCODES + code] = v.y;
        d_cbT[(4*t+2) * NCODES + code] = v.z;
        d_cbT[(4*t+3) * NCODES + code] = v.w;
    }
    d_csq[code] = s;
    int chunk = code >> 6, ci = code & 63;
    ((float*)d_cb_blob)[chunk * (CHUNK_BYTES / 4) + 4096 + ci] = -0.5f * s;
}

// ---------------- K0b: codebook -> mma B fragments (fp16 hi/lo split) ----------------
// blob[chunk] layout: u64[(ksl*8 + nt)*32 + lane]; ksl 0..3 = hi(ks), 4..7 = lo(ks)
__global__ void vq_frag(const float* __restrict__ cb) {
    int g = blockIdx.x * blockDim.x + threadIdx.x;   // 32768 threads
    int lane = g & 31, nt = (g >> 5) & 7, ksl = (g >> 8) & 7, chunk = g >> 11;
    int ks = ksl & 3;
    bool want_lo = (ksl >= 4);
    int code = chunk * NCHUNK + nt * 8 + (lane >> 2);
    int k0 = ks * 16 + (lane & 3) * 2;
    const float* row = cb + (size_t)code * NDIM;
    float2 p0 = *(const float2*)(row + k0);
    float2 p1 = *(const float2*)(row + k0 + 8);
    u32 h0, l0, h1, l1;
    split2h(p0.x, p0.y, h0, l0);
    split2h(p1.x, p1.y, h1, l1);
    u32 r0 = want_lo ? l0 : h0;
    u32 r1 = want_lo ? l1 : h1;
    d_cb_blob[(size_t)chunk * CHUNK_U64 + ((ksl * 8 + nt) * 32 + lane)] =
        (u64)r0 | ((u64)r1 << 32);
}

// ---------------- K1: HMMA screen ----------------
__global__ void __launch_bounds__(256, 2)
vq_screen(const float* __restrict__ inputs) {
    extern __shared__ char smem[];
    const u32 sbase = smem_u32(smem);
    const int tid = threadIdx.x, wid = tid >> 5, lane = tid & 31;
    const int q = lane & 3, rg = lane >> 2;
    const int ctaRow0 = blockIdx.x * MROWS;

    // prefetch chunk 0
    {
        const char* src = (const char*)d_cb_blob;
        for (int j = tid; j < CHUNK_BYTES / 16; j += 256)
            cp16(sbase + (u32)j * 16u, src + (size_t)j * 16);
        cp_commit();
    }

    // build A fragments in registers (fp16 hi/lo split), 2 tiles of 16 rows
    u32 Ahi[2][4][4], Alo[2][4][4];
    #pragma unroll
    for (int t = 0; t < 2; t++) {
        const float* pA = inputs + (size_t)(ctaRow0 + wid * 32 + t * 16 + rg) * NDIM;
        const float* pB = pA + 8 * NDIM;
        #pragma unroll
        for (int ks = 0; ks < 4; ks++) {
            int k0 = ks * 16 + q * 2;
            float2 a0 = *(const float2*)(pA + k0);
            float2 a1 = *(const float2*)(pB + k0);
            float2 a2 = *(const float2*)(pA + k0 + 8);
            float2 a3 = *(const float2*)(pB + k0 + 8);
            split2h(a0.x, a0.y, Ahi[t][ks][0], Alo[t][ks][0]);
            split2h(a1.x, a1.y, Ahi[t][ks][1], Alo[t][ks][1]);
            split2h(a2.x, a2.y, Ahi[t][ks][2], Alo[t][ks][2]);
            split2h(a3.x, a3.y, Ahi[t][ks][3], Alo[t][ks][3]);
        }
    }

    float b1[4], b2[4];
    int   i1[4];
    #pragma unroll
    for (int s = 0; s < 4; s++) { b1[s] = -3.4e38f; b2[s] = -3.4e38f; i1[s] = 0; }

    for (int c = 0; c < NCHUNKS; c++) {
        if (c + 1 < NCHUNKS) {
            u32 dst = sbase + (u32)((c + 1) & 1) * CHUNK_BYTES;
            const char* src = (const char*)d_cb_blob + (size_t)(c + 1) * CHUNK_BYTES;
            for (int j = tid; j < CHUNK_BYTES / 16; j += 256)
                cp16(dst + (u32)j * 16u, src + (size_t)j * 16);
            cp_commit();
            asm volatile("cp.async.wait_group 1;" ::: "memory");
        } else {
            asm volatile("cp.async.wait_group 0;" ::: "memory");
        }
        __syncthreads();

        const u32 bbase = sbase + (u32)(c & 1) * CHUNK_BYTES;
        const int cbase = c * NCHUNK;

        #pragma unroll 2
        for (int np = 0; np < 4; np++) {
            const int nt0 = 2 * np, nt1 = nt0 + 1;
            float C00[4] = {0,0,0,0}, C01[4] = {0,0,0,0};
            float C10[4] = {0,0,0,0}, C11[4] = {0,0,0,0};
            u32 X00[2] = {0,0}, X01[2] = {0,0}, X10[2] = {0,0}, X11[2] = {0,0};
            u32 x0, x1, y0, y1;
            #pragma unroll
            for (int ks = 0; ks < 4; ks++) {      // B = hi_c : hi.hi in f32, lo_x.hi_c in f16
                lds64(bbase + (u32)(((ks * 8 + nt0) * 32 + lane) * 8), x0, x1);
                lds64(bbase + (u32)(((ks * 8 + nt1) * 32 + lane) * 8), y0, y1);
                mma_f32(C00, Ahi[0][ks], x0, x1);
                mma_f32(C01, Ahi[0][ks], y0, y1);
                mma_f32(C10, Ahi[1][ks], x0, x1);
                mma_f32(C11, Ahi[1][ks], y0, y1);
                mma_f16(X00, Alo[0][ks], x0, x1);
                mma_f16(X01, Alo[0][ks], y0, y1);
                mma_f16(X10, Alo[1][ks], x0, x1);
                mma_f16(X11, Alo[1][ks], y0, y1);
            }
            #pragma unroll
            for (int ks = 0; ks < 4; ks++) {      // B = lo_c : hi_x.lo_c in f16
                lds64(bbase + (u32)((((4 + ks) * 8 + nt0) * 32 + lane) * 8), x0, x1);
                lds64(bbase + (u32)((((4 + ks) * 8 + nt1) * 32 + lane) * 8), y0, y1);
                mma_f16(X00, Ahi[0][ks], x0, x1);
                mma_f16(X01, Ahi[0][ks], y0, y1);
                mma_f16(X10, Ahi[1][ks], x0, x1);
                mma_f16(X11, Ahi[1][ks], y0, y1);
            }
            // epilogue: scores = C + cross + csqh ; per-thread top-2
            float q00, q01, q10, q11;
            ldsf2(bbase + 16384u + (u32)((nt0 * 8 + q * 2) * 4), q00, q01);
            ldsf2(bbase + 16384u + (u32)((nt1 * 8 + q * 2) * 4), q10, q11);
            const int n00 = cbase + nt0 * 8 + q * 2;
            const int n10 = cbase + nt1 * 8 + q * 2;

            float2 u, v;
            u = __half22float2(*reinterpret_cast<__half2*>(&X00[0]));
            v = __half22float2(*reinterpret_cast<__half2*>(&X00[1]));
            upd(C00[0] + u.x + q00, n00,     b1[0], b2[0], i1[0]);
            upd(C00[1] + u.y + q01, n00 + 1, b1[0], b2[0], i1[0]);
            upd(C00[2] + v.x + q00, n00,     b1[1], b2[1], i1[1]);
            upd(C00[3] + v.y + q01, n00 + 1, b1[1], b2[1], i1[1]);
            u = __half22float2(*reinterpret_cast<__half2*>(&X01[0]));
            v = __half22float2(*reinterpret_cast<__half2*>(&X01[1]));
            upd(C01[0] + u.x + q10, n10,     b1[0], b2[0], i1[0]);
            upd(C01[1] + u.y + q11, n10 + 1, b1[0], b2[0], i1[0]);
            upd(C01[2] + v.x + q10, n10,     b1[1], b2[1], i1[1]);
            upd(C01[3] + v.y + q11, n10 + 1, b1[1], b2[1], i1[1]);
            u = __half22float2(*reinterpret_cast<__half2*>(&X10[0]));
            v = __half22float2(*reinterpret_cast<__half2*>(&X10[1]));
            upd(C10[0] + u.x + q00, n00,     b1[2], b2[2], i1[2]);
            upd(C10[1] + u.y + q01, n00 + 1, b1[2], b2[2], i1[2]);
            upd(C10[2] + v.x + q00, n00,     b1[3], b2[3], i1[3]);
            upd(C10[3] + v.y + q01, n00 + 1, b1[3], b2[3], i1[3]);
            u = __half22float2(*reinterpret_cast<__half2*>(&X11[0]));
            v = __half22float2(*reinterpret_cast<__half2*>(&X11[1]));
            upd(C11[0] + u.x + q10, n10,     b1[2], b2[2], i1[2]);
            upd(C11[1] + u.y + q11, n10 + 1, b1[2], b2[2], i1[2]);
            upd(C11[2] + v.x + q10, n10,     b1[3], b2[3], i1[3]);
            upd(C11[3] + v.y + q11, n10 + 1, b1[3], b2[3], i1[3]);
        }
        __syncthreads();
    }

    // merge top-2 across the 4 lanes sharing each row
    #pragma unroll
    for (int o = 1; o <= 2; o <<= 1) {
        #pragma unroll
        for (int s = 0; s < 4; s++) {
            float o1 = __shfl_xor_sync(0xffffffffu, b1[s], o);
            float o2 = __shfl_xor_sync(0xffffffffu, b2[s], o);
            int   oi = __shfl_xor_sync(0xffffffffu, i1[s], o);
            float mn = fminf(b1[s], o1);
            b2[s] = fmaxf(fmaxf(b2[s], o2), mn);
            if (o1 > b1[s]) { b1[s] = o1; i1[s] = oi; }
        }
    }

    if (q == 0) {
        #pragma unroll
        for (int s = 0; s < 4; s++) {
            int t = s >> 1, h = s & 1;
            int row = ctaRow0 + wid * 32 + t * 16 + h * 8 + rg;
            if (b1[s] - b2[s] < MARGIN_S) {
                d_bestkey[row] = ~0ULL;
                int p = atomicAdd(&d_nflag, 1);
                d_flag[p] = row;
            } else {
                d_bestkey[row] = (u64)(u32)i1[s];
            }
        }
    }
}

// ---------------- K2: exact refine of flagged rows, coalesced over cbT ----------------
__global__ void vq_refine(const float* __restrict__ inputs) {
    const int n     = d_nflag;
    const int nwarp = (gridDim.x * blockDim.x) >> 5;
    const int w     = (blockIdx.x * blockDim.x + threadIdx.x) >> 5;
    const int lane  = threadIdx.x & 31;
    const int nitems = n * 32;                 // 32 code-blocks of 32 per row
    for (int item = w; item < nitems; item += nwarp) {
        const int row = d_flag[item >> 5];
        const int c   = ((item & 31) << 5) + lane;
        const float* x = inputs + (size_t)row * NDIM;
        float acc = 0.f, xs = 0.f;
        #pragma unroll
        for (int d = 0; d < NDIM; d++) {
            float xv = __ldg(x + d);
            acc = __fmaf_rn(xv, d_cbT[d * NCODES + c], acc);
            xs  = __fmaf_rn(xv, xv, xs);
        }
        float dist = __fadd_rn(__fsub_rn(xs, __fmul_rn(2.0f, acc)), d_csq[c]);
        dist = fmaxf(dist, 0.0f);
        u64 key = ((u64)__float_as_uint(dist) << 32) | (u32)c;
        #pragma unroll
        for (int o = 16; o; o >>= 1) {
            u64 ok = __shfl_xor_sync(0xffffffffu, key, o);
            key = (ok < key) ? ok : key;
        }
        if (lane == 0) atomicMin(&d_bestkey[row], key);
    }
}

// ---------------- K3: gather ----------------
__global__ void vq_gather(const float* __restrict__ cb, float* __restrict__ out) {
    int t = blockIdx.x * blockDim.x + threadIdx.x;
    int row = t >> 2, part = t & 3;
    u32 bi = (u32)(d_bestkey[row] & 0xFFFFFFFFu);
    const float4* s = (const float4*)cb + (size_t)bi * 16 + part * 4;
    float4* o = (float4*)out + (size_t)row * 16 + part * 4;
    o[0] = s[0]; o[1] = s[1]; o[2] = s[2]; o[3] = s[3];
}

// ---------------- host launch ----------------
extern "C" void kernel_launch(void* const* d_in, const int* in_sizes, int n_in,
                              void* d_out, int out_size)
{
    const float* inputs   = (const float*)d_in[0];
    const float* codebook = (const float*)d_in[1];
    float* out = (float*)d_out;

    cudaFuncSetAttribute(vq_screen, cudaFuncAttributeMaxDynamicSharedMemorySize, SMEM_DYN);

    vq_csq   <<<NCODES / 256, 256>>>(codebook);
    vq_frag  <<<128, 256>>>(codebook);
    vq_screen<<<NROWS / MROWS, 256, SMEM_DYN>>>(inputs);
    vq_refine<<<256, 256>>>(inputs);
    vq_gather<<<NROWS * 4 / 256, 256>>>(codebook, out);
}

// round 7
// speedup vs baseline: 4.6579x; 1.5418x over previous
#include <cuda_runtime.h>
#include <cuda_fp16.h>
#include <cstdint>

typedef unsigned long long u64;
typedef unsigned int u32;

#define NROWS    262144
#define NCODES   1024
#define NDIM     64
#define MROWS    256              // rows per screen CTA
#define NCHUNK   64               // codes per chunk
#define NCHUNKS  16
#define CHUNK_BYTES 8448          // 8KB hi frags + 256B csqh
#define CHUNK_U64   1056
#define SMEM_DYN (2 * CHUNK_BYTES)
#define MARGIN_S 0.035f           // score-gap margin (distance gap 0.07)
#define RREP     37               // refine replicas (8*37 = 296 CTAs)

// ---- device globals (no allocs allowed) ----
__device__ u64   d_bestkey[NROWS];               // (distbits<<32)|code ; unflagged: code only
__device__ int   d_flag[NROWS];
__device__ int   d_nflag;
__device__ u64   d_cb_blob[NCHUNKS * CHUNK_U64]; // fragment-ordered fp16 codebook (hi) + csqh
__device__ float d_csq[NCODES];
__device__ float d_cbT[NDIM * NCODES];           // transposed codebook for refine
__device__ float d_xsq[NROWS];                   // ||x||^2 for flagged rows

// ---------------- helpers ----------------
__device__ __forceinline__ u32 smem_u32(const void* p) {
    u32 a; asm("{ .reg .u64 t; cvta.to.shared.u64 t, %1; cvt.u32.u64 %0, t; }" : "=r"(a) : "l"(p));
    return a;
}
__device__ __forceinline__ u32 pack2h(float a0, float a1) {
    __half h0 = __float2half_rn(a0), h1 = __float2half_rn(a1);
    return (u32)*(unsigned short*)&h0 | ((u32)*(unsigned short*)&h1 << 16);
}
__device__ __forceinline__ void mma_f32(float* c, const u32* a, u32 b0, u32 b1) {
    asm volatile("mma.sync.aligned.m16n8k16.row.col.f32.f16.f16.f32 "
        "{%0,%1,%2,%3}, {%4,%5,%6,%7}, {%8,%9}, {%0,%1,%2,%3};"
        : "+f"(c[0]), "+f"(c[1]), "+f"(c[2]), "+f"(c[3])
        : "r"(a[0]), "r"(a[1]), "r"(a[2]), "r"(a[3]), "r"(b0), "r"(b1));
}
__device__ __forceinline__ void lds64(u32 addr, u32& x, u32& y) {
    asm volatile("ld.shared.v2.u32 {%0,%1}, [%2];" : "=r"(x), "=r"(y) : "r"(addr));
}
__device__ __forceinline__ void ldsf2(u32 addr, float& x, float& y) {
    asm volatile("ld.shared.v2.f32 {%0,%1}, [%2];" : "=f"(x), "=f"(y) : "r"(addr));
}
__device__ __forceinline__ void cp16(u32 dst, const void* src) {
    asm volatile("cp.async.cg.shared.global [%0], [%1], 16;" :: "r"(dst), "l"(src) : "memory");
}
__device__ __forceinline__ void cp_commit() { asm volatile("cp.async.commit_group;" ::: "memory"); }
__device__ __forceinline__ void upd(float s, int code, float& b1, float& b2, int& i1) {
    if (s > b1) { b2 = b1; b1 = s; i1 = code; } else b2 = fmaxf(b2, s);
}

// ---------------- K0a: exact csq + csqh into blob + cbT, reset flag count ----------------
__global__ void vq_csq(const float* __restrict__ cb) {
    int code = blockIdx.x * blockDim.x + threadIdx.x;
    if (code == 0) d_nflag = 0;
    if (code >= NCODES) return;
    const float4* c4 = (const float4*)(cb + (size_t)code * NDIM);
    float s = 0.f;
    #pragma unroll
    for (int t = 0; t < 16; t++) {
        float4 v = c4[t];
        s = __fadd_rn(s, __fmul_rn(v.x, v.x));
        s = __fadd_rn(s, __fmul_rn(v.y, v.y));
        s = __fadd_rn(s, __fmul_rn(v.z, v.z));
        s = __fadd_rn(s, __fmul_rn(v.w, v.w));
        d_cbT[(4*t+0) * NCODES + code] = v.x;
        d_cbT[(4*t+1) * NCODES + code] = v.y;
        d_cbT[(4*t+2) * NCODES + code] = v.z;
        d_cbT[(4*t+3) * NCODES + code] = v.w;
    }
    d_csq[code] = s;
    int chunk = code >> 6, ci = code & 63;
    ((float*)d_cb_blob)[chunk * (CHUNK_BYTES / 4) + 2048 + ci] = -0.5f * s;
}

// ---------------- K0b: codebook -> mma B fragments (fp16 hi only) ----------------
// blob[chunk] layout: u64[(ks*8 + nt)*32 + lane]
__global__ void vq_frag(const float* __restrict__ cb) {
    int g = blockIdx.x * blockDim.x + threadIdx.x;   // 16384 threads
    int lane = g & 31, nt = (g >> 5) & 7, ks = (g >> 8) & 3, chunk = g >> 10;
    int code = chunk * NCHUNK + nt * 8 + (lane >> 2);
    int k0 = ks * 16 + (lane & 3) * 2;
    const float* row = cb + (size_t)code * NDIM;
    float2 p0 = *(const float2*)(row + k0);
    float2 p1 = *(const float2*)(row + k0 + 8);
    u32 r0 = pack2h(p0.x, p0.y);
    u32 r1 = pack2h(p1.x, p1.y);
    d_cb_blob[(size_t)chunk * CHUNK_U64 + ((ks * 8 + nt) * 32 + lane)] =
        (u64)r0 | ((u64)r1 << 32);
}

// ---------------- K1: HMMA screen (single fp16 product) ----------------
__global__ void __launch_bounds__(256, 2)
vq_screen(const float* __restrict__ inputs) {
    extern __shared__ char smem[];
    const u32 sbase = smem_u32(smem);
    const int tid = threadIdx.x, wid = tid >> 5, lane = tid & 31;
    const int q = lane & 3, rg = lane >> 2;
    const int ctaRow0 = blockIdx.x * MROWS;

    // prefetch chunk 0
    {
        const char* src = (const char*)d_cb_blob;
        for (int j = tid; j < CHUNK_BYTES / 16; j += 256)
            cp16(sbase + (u32)j * 16u, src + (size_t)j * 16);
        cp_commit();
    }

    // build A fragments in registers (fp16), 2 tiles of 16 rows
    u32 Ahi[2][4][4];
    #pragma unroll
    for (int t = 0; t < 2; t++) {
        const float* pA = inputs + (size_t)(ctaRow0 + wid * 32 + t * 16 + rg) * NDIM;
        const float* pB = pA + 8 * NDIM;
        #pragma unroll
        for (int ks = 0; ks < 4; ks++) {
            int k0 = ks * 16 + q * 2;
            float2 a0 = *(const float2*)(pA + k0);
            float2 a1 = *(const float2*)(pB + k0);
            float2 a2 = *(const float2*)(pA + k0 + 8);
            float2 a3 = *(const float2*)(pB + k0 + 8);
            Ahi[t][ks][0] = pack2h(a0.x, a0.y);
            Ahi[t][ks][1] = pack2h(a1.x, a1.y);
            Ahi[t][ks][2] = pack2h(a2.x, a2.y);
            Ahi[t][ks][3] = pack2h(a3.x, a3.y);
        }
    }

    float b1[4], b2[4];
    int   i1[4];
    #pragma unroll
    for (int s = 0; s < 4; s++) { b1[s] = -3.4e38f; b2[s] = -3.4e38f; i1[s] = 0; }

    for (int c = 0; c < NCHUNKS; c++) {
        if (c + 1 < NCHUNKS) {
            u32 dst = sbase + (u32)((c + 1) & 1) * CHUNK_BYTES;
            const char* src = (const char*)d_cb_blob + (size_t)(c + 1) * CHUNK_BYTES;
            for (int j = tid; j < CHUNK_BYTES / 16; j += 256)
                cp16(dst + (u32)j * 16u, src + (size_t)j * 16);
            cp_commit();
            asm volatile("cp.async.wait_group 1;" ::: "memory");
        } else {
            asm volatile("cp.async.wait_group 0;" ::: "memory");
        }
        __syncthreads();

        const u32 bbase = sbase + (u32)(c & 1) * CHUNK_BYTES;
        const int cbase = c * NCHUNK;

        #pragma unroll
        for (int np = 0; np < 4; np++) {
            const int nt0 = 2 * np, nt1 = nt0 + 1;
            float C00[4] = {0,0,0,0}, C01[4] = {0,0,0,0};
            float C10[4] = {0,0,0,0}, C11[4] = {0,0,0,0};
            u32 x0, x1, y0, y1;
            #pragma unroll
            for (int ks = 0; ks < 4; ks++) {
                lds64(bbase + (u32)(((ks * 8 + nt0) * 32 + lane) * 8), x0, x1);
                lds64(bbase + (u32)(((ks * 8 + nt1) * 32 + lane) * 8), y0, y1);
                mma_f32(C00, Ahi[0][ks], x0, x1);
                mma_f32(C01, Ahi[0][ks], y0, y1);
                mma_f32(C10, Ahi[1][ks], x0, x1);
                mma_f32(C11, Ahi[1][ks], y0, y1);
            }
            // epilogue: scores = C + csqh ; per-thread top-2
            float q00, q01, q10, q11;
            ldsf2(bbase + 8192u + (u32)((nt0 * 8 + q * 2) * 4), q00, q01);
            ldsf2(bbase + 8192u + (u32)((nt1 * 8 + q * 2) * 4), q10, q11);
            const int n00 = cbase + nt0 * 8 + q * 2;
            const int n10 = cbase + nt1 * 8 + q * 2;
            upd(C00[0] + q00, n00,     b1[0], b2[0], i1[0]);
            upd(C00[1] + q01, n00 + 1, b1[0], b2[0], i1[0]);
            upd(C00[2] + q00, n00,     b1[1], b2[1], i1[1]);
            upd(C00[3] + q01, n00 + 1, b1[1], b2[1], i1[1]);
            upd(C01[0] + q10, n10,     b1[0], b2[0], i1[0]);
            upd(C01[1] + q11, n10 + 1, b1[0], b2[0], i1[0]);
            upd(C01[2] + q10, n10,     b1[1], b2[1], i1[1]);
            upd(C01[3] + q11, n10 + 1, b1[1], b2[1], i1[1]);
            upd(C10[0] + q00, n00,     b1[2], b2[2], i1[2]);
            upd(C10[1] + q01, n00 + 1, b1[2], b2[2], i1[2]);
            upd(C10[2] + q00, n00,     b1[3], b2[3], i1[3]);
            upd(C10[3] + q01, n00 + 1, b1[3], b2[3], i1[3]);
            upd(C11[0] + q10, n10,     b1[2], b2[2], i1[2]);
            upd(C11[1] + q11, n10 + 1, b1[2], b2[2], i1[2]);
            upd(C11[2] + q10, n10,     b1[3], b2[3], i1[3]);
            upd(C11[3] + q11, n10 + 1, b1[3], b2[3], i1[3]);
        }
        __syncthreads();
    }

    // merge top-2 across the 4 lanes sharing each row
    #pragma unroll
    for (int o = 1; o <= 2; o <<= 1) {
        #pragma unroll
        for (int s = 0; s < 4; s++) {
            float o1 = __shfl_xor_sync(0xffffffffu, b1[s], o);
            float o2 = __shfl_xor_sync(0xffffffffu, b2[s], o);
            int   oi = __shfl_xor_sync(0xffffffffu, i1[s], o);
            float mn = fminf(b1[s], o1);
            b2[s] = fmaxf(fmaxf(b2[s], o2), mn);
            if (o1 > b1[s]) { b1[s] = o1; i1[s] = oi; }
        }
    }

    if (q == 0) {
        #pragma unroll
        for (int s = 0; s < 4; s++) {
            int t = s >> 1, h = s & 1;
            int row = ctaRow0 + wid * 32 + t * 16 + h * 8 + rg;
            if (b1[s] - b2[s] < MARGIN_S) {
                d_bestkey[row] = ~0ULL;
                int p = atomicAdd(&d_nflag, 1);
                d_flag[p] = row;
            } else {
                d_bestkey[row] = (u64)(u32)i1[s];
            }
        }
    }
}

// ---------------- K2a: xs for flagged rows (reference rounding: ascending fmaf) ----------------
__global__ void vq_xsq(const float* __restrict__ inputs) {
    const int n = d_nflag;
    for (int i = blockIdx.x * blockDim.x + threadIdx.x; i < n; i += gridDim.x * blockDim.x) {
        int row = d_flag[i];
        const float* x = inputs + (size_t)row * NDIM;
        float xs = 0.f;
        #pragma unroll
        for (int d = 0; d < NDIM; d++) {
            float xv = __ldg(x + d);
            xs = __fmaf_rn(xv, xv, xs);
        }
        d_xsq[row] = xs;
    }
}

// ---------------- K2b: exact refine, smem code-slices, 4-row quads ----------------
__global__ void __launch_bounds__(256, 2)
vq_refine(const float* __restrict__ inputs) {
    __shared__ float s_cb[NDIM * 128];   // [d][128] slice, 32KB
    __shared__ float s_csq[128];
    const int n = d_nflag;
    if (n == 0) return;
    const int tid  = threadIdx.x, wid = tid >> 5, lane = tid & 31;
    const int slice = blockIdx.x & 7, rep = blockIdx.x >> 3;   // 8 slices x RREP
    const int code0 = slice * 128;

    for (int idx = tid; idx < NDIM * 128; idx += 256)
        s_cb[idx] = d_cbT[(idx >> 7) * NCODES + code0 + (idx & 127)];
    if (tid < 128) s_csq[tid] = d_csq[code0 + tid];
    __syncthreads();

    const int nquads = (n + 3) >> 2;
    const int gw = rep * 8 + wid;                 // 0 .. RREP*8-1
    for (int qd = gw; qd < nquads; qd += RREP * 8) {
        int rows[4]; const float* xp[4]; float xs[4];
        #pragma unroll
        for (int j = 0; j < 4; j++) {
            int fi = 4 * qd + j; if (fi >= n) fi = n - 1;
            rows[j] = d_flag[fi];
            xp[j]   = inputs + (size_t)rows[j] * NDIM;
            xs[j]   = d_xsq[rows[j]];
        }
        float acc[4][4];
        #pragma unroll
        for (int j = 0; j < 4; j++)
            #pragma unroll
            for (int k = 0; k < 4; k++) acc[j][k] = 0.f;

        #pragma unroll 8
        for (int d = 0; d < NDIM; d++) {
            float4 c4 = *(const float4*)&s_cb[d * 128 + lane * 4];
            #pragma unroll
            for (int j = 0; j < 4; j++) {
                float xv = __ldg(xp[j] + d);
                acc[j][0] = __fmaf_rn(xv, c4.x, acc[j][0]);
                acc[j][1] = __fmaf_rn(xv, c4.y, acc[j][1]);
                acc[j][2] = __fmaf_rn(xv, c4.z, acc[j][2]);
                acc[j][3] = __fmaf_rn(xv, c4.w, acc[j][3]);
            }
        }
        #pragma unroll
        for (int j = 0; j < 4; j++) {
            u64 key = ~0ULL;
            #pragma unroll
            for (int k = 0; k < 4; k++) {
                int c = code0 + lane * 4 + k;
                float dist = __fadd_rn(__fsub_rn(xs[j], __fmul_rn(2.0f, acc[j][k])), s_csq[lane * 4 + k]);
                dist = fmaxf(dist, 0.0f);
                u64 kk = ((u64)__float_as_uint(dist) << 32) | (u32)c;
                key = (kk < key) ? kk : key;
            }
            #pragma unroll
            for (int o = 16; o; o >>= 1) {
                u64 ok = __shfl_xor_sync(0xffffffffu, key, o);
                key = (ok < key) ? ok : key;
            }
            if (lane == 0) atomicMin(&d_bestkey[rows[j]], key);
        }
    }
}

// ---------------- K3: gather ----------------
__global__ void vq_gather(const float* __restrict__ cb, float* __restrict__ out) {
    int t = blockIdx.x * blockDim.x + threadIdx.x;
    int row = t >> 2, part = t & 3;
    u32 bi = (u32)(d_bestkey[row] & 0xFFFFFFFFu);
    const float4* s = (const float4*)cb + (size_t)bi * 16 + part * 4;
    float4* o = (float4*)out + (size_t)row * 16 + part * 4;
    o[0] = s[0]; o[1] = s[1]; o[2] = s[2]; o[3] = s[3];
}

// ---------------- host launch ----------------
extern "C" void kernel_launch(void* const* d_in, const int* in_sizes, int n_in,
                              void* d_out, int out_size)
{
    const float* inputs   = (const float*)d_in[0];
    const float* codebook = (const float*)d_in[1];
    float* out = (float*)d_out;

    cudaFuncSetAttribute(vq_screen, cudaFuncAttributeMaxDynamicSharedMemorySize, SMEM_DYN);

    vq_csq   <<<NCODES / 256, 256>>>(codebook);
    vq_frag  <<<64, 256>>>(codebook);
    vq_screen<<<NROWS / MROWS, 256, SMEM_DYN>>>(inputs);
    vq_xsq   <<<128, 256>>>(inputs);
    vq_refine<<<8 * RREP, 256>>>(inputs);
    vq_gather<<<NROWS * 4 / 256, 256>>>(codebook, out);
}

// round 9
// speedup vs baseline: 4.7465x; 1.0190x over previous
#include <cuda_runtime.h>
#include <cuda_fp16.h>
#include <cstdint>

typedef unsigned long long u64;
typedef unsigned int u32;

#define NROWS    262144
#define NCODES   1024
#define NDIM     64
#define MROWS    256              // rows per screen CTA
#define NCHUNK   64               // codes per chunk
#define NCHUNKS  16
#define CHUNK_BYTES 8448          // 8KB hi frags + 256B csqh
#define CHUNK_U64   1056
#define SMEM_DYN (2 * CHUNK_BYTES)
#define MARGIN_S 0.035f           // score-gap margin (distance gap 0.07)
#define RREP     37               // refine replicas (8*37 = 296 CTAs)

// ---- device globals (no allocs allowed) ----
__device__ u64   d_bestkey[NROWS];               // flagged rows: (distbits<<32)|code
__device__ int   d_flag[NROWS];
__device__ int   d_nflag;
__device__ u64   d_cb_blob[NCHUNKS * CHUNK_U64]; // fragment-ordered fp16 codebook (hi) + csqh
__device__ float d_csq[NCODES];
__device__ float d_cbT[NDIM * NCODES];           // transposed codebook for refine
__device__ float d_xsq[NROWS];                   // ||x||^2, ROUND-7 rounding (ascending fmaf)

// ---------------- helpers ----------------
__device__ __forceinline__ u32 smem_u32(const void* p) {
    u32 a; asm("{ .reg .u64 t; cvta.to.shared.u64 t, %1; cvt.u32.u64 %0, t; }" : "=r"(a) : "l"(p));
    return a;
}
__device__ __forceinline__ u32 pack2h(float a0, float a1) {
    __half h0 = __float2half_rn(a0), h1 = __float2half_rn(a1);
    return (u32)*(unsigned short*)&h0 | ((u32)*(unsigned short*)&h1 << 16);
}
__device__ __forceinline__ void mma_f32(float* c, const u32* a, u32 b0, u32 b1) {
    asm volatile("mma.sync.aligned.m16n8k16.row.col.f32.f16.f16.f32 "
        "{%0,%1,%2,%3}, {%4,%5,%6,%7}, {%8,%9}, {%0,%1,%2,%3};"
        : "+f"(c[0]), "+f"(c[1]), "+f"(c[2]), "+f"(c[3])
        : "r"(a[0]), "r"(a[1]), "r"(a[2]), "r"(a[3]), "r"(b0), "r"(b1));
}
__device__ __forceinline__ void lds64(u32 addr, u32& x, u32& y) {
    asm volatile("ld.shared.v2.u32 {%0,%1}, [%2];" : "=r"(x), "=r"(y) : "r"(addr));
}
__device__ __forceinline__ void ldsf2(u32 addr, float& x, float& y) {
    asm volatile("ld.shared.v2.f32 {%0,%1}, [%2];" : "=f"(x), "=f"(y) : "r"(addr));
}
__device__ __forceinline__ void cp16(u32 dst, const void* src) {
    asm volatile("cp.async.cg.shared.global [%0], [%1], 16;" :: "r"(dst), "l"(src) : "memory");
}
__device__ __forceinline__ void cp_commit() { asm volatile("cp.async.commit_group;" ::: "memory"); }
__device__ __forceinline__ void upd(float s, int code, float& b1, float& b2, int& i1) {
    if (s > b1) { b2 = b1; b1 = s; i1 = code; } else b2 = fmaxf(b2, s);
}

// ---------------- K0a: exact csq + csqh into blob + cbT, reset flag count ----------------
__global__ void vq_csq(const float* __restrict__ cb) {
    int code = blockIdx.x * blockDim.x + threadIdx.x;
    if (code == 0) d_nflag = 0;
    if (code >= NCODES) return;
    const float4* c4 = (const float4*)(cb + (size_t)code * NDIM);
    float s = 0.f;
    #pragma unroll
    for (int t = 0; t < 16; t++) {
        float4 v = c4[t];
        s = __fadd_rn(s, __fmul_rn(v.x, v.x));
        s = __fadd_rn(s, __fmul_rn(v.y, v.y));
        s = __fadd_rn(s, __fmul_rn(v.z, v.z));
        s = __fadd_rn(s, __fmul_rn(v.w, v.w));
        d_cbT[(4*t+0) * NCODES + code] = v.x;
        d_cbT[(4*t+1) * NCODES + code] = v.y;
        d_cbT[(4*t+2) * NCODES + code] = v.z;
        d_cbT[(4*t+3) * NCODES + code] = v.w;
    }
    d_csq[code] = s;
    int chunk = code >> 6, ci = code & 63;
    ((float*)d_cb_blob)[chunk * (CHUNK_BYTES / 4) + 2048 + ci] = -0.5f * s;
}

// ---------------- K0b: codebook -> mma B fragments (fp16 hi only) ----------------
__global__ void vq_frag(const float* __restrict__ cb) {
    int g = blockIdx.x * blockDim.x + threadIdx.x;   // 16384 threads
    int lane = g & 31, nt = (g >> 5) & 7, ks = (g >> 8) & 3, chunk = g >> 10;
    int code = chunk * NCHUNK + nt * 8 + (lane >> 2);
    int k0 = ks * 16 + (lane & 3) * 2;
    const float* row = cb + (size_t)code * NDIM;
    float2 p0 = *(const float2*)(row + k0);
    float2 p1 = *(const float2*)(row + k0 + 8);
    d_cb_blob[(size_t)chunk * CHUNK_U64 + ((ks * 8 + nt) * 32 + lane)] =
        (u64)pack2h(p0.x, p0.y) | ((u64)pack2h(p1.x, p1.y) << 32);
}

// ---------------- K1: HMMA screen (single fp16 product) + direct output ----------------
__global__ void __launch_bounds__(256, 2)
vq_screen(const float* __restrict__ inputs, const float* __restrict__ cb,
          float* __restrict__ out) {
    extern __shared__ char smem[];
    const u32 sbase = smem_u32(smem);
    const int tid = threadIdx.x, wid = tid >> 5, lane = tid & 31;
    const int q = lane & 3, rg = lane >> 2;
    const int ctaRow0 = blockIdx.x * MROWS;

    // prefetch chunk 0
    {
        const char* src = (const char*)d_cb_blob;
        for (int j = tid; j < CHUNK_BYTES / 16; j += 256)
            cp16(sbase + (u32)j * 16u, src + (size_t)j * 16);
        cp_commit();
    }

    // build A fragments in registers (fp16), 2 tiles of 16 rows
    u32 Ahi[2][4][4];
    #pragma unroll
    for (int t = 0; t < 2; t++) {
        const float* pA = inputs + (size_t)(ctaRow0 + wid * 32 + t * 16 + rg) * NDIM;
        const float* pB = pA + 8 * NDIM;
        #pragma unroll
        for (int ks = 0; ks < 4; ks++) {
            int k0 = ks * 16 + q * 2;
            float2 a0 = *(const float2*)(pA + k0);
            float2 a1 = *(const float2*)(pB + k0);
            float2 a2 = *(const float2*)(pA + k0 + 8);
            float2 a3 = *(const float2*)(pB + k0 + 8);
            Ahi[t][ks][0] = pack2h(a0.x, a0.y);
            Ahi[t][ks][1] = pack2h(a1.x, a1.y);
            Ahi[t][ks][2] = pack2h(a2.x, a2.y);
            Ahi[t][ks][3] = pack2h(a3.x, a3.y);
        }
    }

    float b1[4], b2[4];
    int   i1[4];
    #pragma unroll
    for (int s = 0; s < 4; s++) { b1[s] = -3.4e38f; b2[s] = -3.4e38f; i1[s] = 0; }

    for (int c = 0; c < NCHUNKS; c++) {
        if (c + 1 < NCHUNKS) {
            u32 dst = sbase + (u32)((c + 1) & 1) * CHUNK_BYTES;
            const char* src = (const char*)d_cb_blob + (size_t)(c + 1) * CHUNK_BYTES;
            for (int j = tid; j < CHUNK_BYTES / 16; j += 256)
                cp16(dst + (u32)j * 16u, src + (size_t)j * 16);
            cp_commit();
            asm volatile("cp.async.wait_group 1;" ::: "memory");
        } else {
            asm volatile("cp.async.wait_group 0;" ::: "memory");
        }
        __syncthreads();

        const u32 bbase = sbase + (u32)(c & 1) * CHUNK_BYTES;
        const int cbase = c * NCHUNK;

        #pragma unroll
        for (int np = 0; np < 4; np++) {
            const int nt0 = 2 * np, nt1 = nt0 + 1;
            float C00[4] = {0,0,0,0}, C01[4] = {0,0,0,0};
            float C10[4] = {0,0,0,0}, C11[4] = {0,0,0,0};
            u32 x0, x1, y0, y1;
            #pragma unroll
            for (int ks = 0; ks < 4; ks++) {
                lds64(bbase + (u32)(((ks * 8 + nt0) * 32 + lane) * 8), x0, x1);
                lds64(bbase + (u32)(((ks * 8 + nt1) * 32 + lane) * 8), y0, y1);
                mma_f32(C00, Ahi[0][ks], x0, x1);
                mma_f32(C01, Ahi[0][ks], y0, y1);
                mma_f32(C10, Ahi[1][ks], x0, x1);
                mma_f32(C11, Ahi[1][ks], y0, y1);
            }
            float q00, q01, q10, q11;
            ldsf2(bbase + 8192u + (u32)((nt0 * 8 + q * 2) * 4), q00, q01);
            ldsf2(bbase + 8192u + (u32)((nt1 * 8 + q * 2) * 4), q10, q11);
            const int n00 = cbase + nt0 * 8 + q * 2;
            const int n10 = cbase + nt1 * 8 + q * 2;
            upd(C00[0] + q00, n00,     b1[0], b2[0], i1[0]);
            upd(C00[1] + q01, n00 + 1, b1[0], b2[0], i1[0]);
            upd(C00[2] + q00, n00,     b1[1], b2[1], i1[1]);
            upd(C00[3] + q01, n00 + 1, b1[1], b2[1], i1[1]);
            upd(C01[0] + q10, n10,     b1[0], b2[0], i1[0]);
            upd(C01[1] + q11, n10 + 1, b1[0], b2[0], i1[0]);
            upd(C01[2] + q10, n10,     b1[1], b2[1], i1[1]);
            upd(C01[3] + q11, n10 + 1, b1[1], b2[1], i1[1]);
            upd(C10[0] + q00, n00,     b1[2], b2[2], i1[2]);
            upd(C10[1] + q01, n00 + 1, b1[2], b2[2], i1[2]);
            upd(C10[2] + q00, n00,     b1[3], b2[3], i1[3]);
            upd(C10[3] + q01, n00 + 1, b1[3], b2[3], i1[3]);
            upd(C11[0] + q10, n10,     b1[2], b2[2], i1[2]);
            upd(C11[1] + q11, n10 + 1, b1[2], b2[2], i1[2]);
            upd(C11[2] + q10, n10,     b1[3], b2[3], i1[3]);
            upd(C11[3] + q11, n10 + 1, b1[3], b2[3], i1[3]);
        }
        __syncthreads();
    }

    // merge top-2 across the 4 lanes sharing each row
    #pragma unroll
    for (int o = 1; o <= 2; o <<= 1) {
        #pragma unroll
        for (int s = 0; s < 4; s++) {
            float o1 = __shfl_xor_sync(0xffffffffu, b1[s], o);
            float o2 = __shfl_xor_sync(0xffffffffu, b2[s], o);
            int   oi = __shfl_xor_sync(0xffffffffu, i1[s], o);
            float mn = fminf(b1[s], o1);
            b2[s] = fmaxf(fmaxf(b2[s], o2), mn);
            if (o1 > b1[s]) { b1[s] = o1; i1[s] = oi; }
        }
    }

    // finalize: unflagged rows -> write output directly (all 4 lanes, consistent i1
    // since any tie forces gap==0 -> flagged); flagged -> queue for refine.
    #pragma unroll
    for (int s = 0; s < 4; s++) {
        int t = s >> 1, h = s & 1;
        int row = ctaRow0 + wid * 32 + t * 16 + h * 8 + rg;
        if (b1[s] - b2[s] < MARGIN_S) {
            if (q == 0) {
                d_bestkey[row] = ~0ULL;
                int p = atomicAdd(&d_nflag, 1);
                d_flag[p] = row;
            }
        } else {
            const float4* src = (const float4*)cb + (size_t)i1[s] * 16 + q * 4;
            float4* dst = (float4*)out + (size_t)row * 16 + q * 4;
            dst[0] = src[0]; dst[1] = src[1]; dst[2] = src[2]; dst[3] = src[3];
        }
    }
}

// ---------------- K2a: xs for flagged rows (ROUND-7 bitwise: ascending fmaf) ----------------
__global__ void vq_xsq(const float* __restrict__ inputs) {
    const int n = d_nflag;
    for (int i = blockIdx.x * blockDim.x + threadIdx.x; i < n; i += gridDim.x * blockDim.x) {
        int row = d_flag[i];
        const float* x = inputs + (size_t)row * NDIM;
        float xs = 0.f;
        #pragma unroll
        for (int d = 0; d < NDIM; d++) {
            float xv = __ldg(x + d);
            xs = __fmaf_rn(xv, xv, xs);
        }
        d_xsq[row] = xs;
    }
}

// ---------------- K2b: exact refine (ROUND-7 bitwise scalar), smem slices, 4-row quads ----------------
__global__ void __launch_bounds__(256, 2)
vq_refine(const float* __restrict__ inputs) {
    __shared__ float s_cb[NDIM * 128];   // [d][128] slice, 32KB
    __shared__ float s_csq[128];
    const int n = d_nflag;
    if (n == 0) return;
    const int tid  = threadIdx.x, wid = tid >> 5, lane = tid & 31;
    const int slice = blockIdx.x & 7, rep = blockIdx.x >> 3;   // 8 slices x RREP
    const int code0 = slice * 128;

    for (int idx = tid; idx < NDIM * 128; idx += 256)
        s_cb[idx] = d_cbT[(idx >> 7) * NCODES + code0 + (idx & 127)];
    if (tid < 128) s_csq[tid] = d_csq[code0 + tid];
    __syncthreads();

    const int nquads = (n + 3) >> 2;
    const int gw = rep * 8 + wid;
    for (int qd = gw; qd < nquads; qd += RREP * 8) {
        int rows[4]; const float* xp[4]; float xs[4];
        #pragma unroll
        for (int j = 0; j < 4; j++) {
            int fi = 4 * qd + j; if (fi >= n) fi = n - 1;
            rows[j] = d_flag[fi];
            xp[j]   = inputs + (size_t)rows[j] * NDIM;
            xs[j]   = d_xsq[rows[j]];
        }
        float acc[4][4];
        #pragma unroll
        for (int j = 0; j < 4; j++)
            #pragma unroll
            for (int k = 0; k < 4; k++) acc[j][k] = 0.f;

        #pragma unroll 8
        for (int d = 0; d < NDIM; d++) {
            float4 c4 = *(const float4*)&s_cb[d * 128 + lane * 4];
            #pragma unroll
            for (int j = 0; j < 4; j++) {
                float xv = __ldg(xp[j] + d);
                acc[j][0] = __fmaf_rn(xv, c4.x, acc[j][0]);
                acc[j][1] = __fmaf_rn(xv, c4.y, acc[j][1]);
                acc[j][2] = __fmaf_rn(xv, c4.z, acc[j][2]);
                acc[j][3] = __fmaf_rn(xv, c4.w, acc[j][3]);
            }
        }
        #pragma unroll
        for (int j = 0; j < 4; j++) {
            u64 key = ~0ULL;
            #pragma unroll
            for (int k = 0; k < 4; k++) {
                int c = code0 + lane * 4 + k;
                float dist = __fadd_rn(__fsub_rn(xs[j], __fmul_rn(2.0f, acc[j][k])), s_csq[lane * 4 + k]);
                dist = fmaxf(dist, 0.0f);
                u64 kk = ((u64)__float_as_uint(dist) << 32) | (u32)c;
                key = (kk < key) ? kk : key;
            }
            #pragma unroll
            for (int o = 16; o; o >>= 1) {
                u64 ok = __shfl_xor_sync(0xffffffffu, key, o);
                key = (ok < key) ? ok : key;
            }
            if (lane == 0) atomicMin(&d_bestkey[rows[j]], key);
        }
    }
}

// ---------------- K3: gather flagged rows only ----------------
__global__ void vq_fgather(const float* __restrict__ cb, float* __restrict__ out) {
    const int total = d_nflag * 4;
    const int stride = gridDim.x * blockDim.x;
    for (int t = blockIdx.x * blockDim.x + threadIdx.x; t < total; t += stride) {
        int fi = t >> 2, part = t & 3;
        int row = d_flag[fi];
        u32 bi = (u32)(d_bestkey[row] & 0xFFFFFFFFu);
        const float4* s = (const float4*)cb + (size_t)bi * 16 + part * 4;
        float4* o = (float4*)out + (size_t)row * 16 + part * 4;
        o[0] = s[0]; o[1] = s[1]; o[2] = s[2]; o[3] = s[3];
    }
}

// ---------------- host launch ----------------
extern "C" void kernel_launch(void* const* d_in, const int* in_sizes, int n_in,
                              void* d_out, int out_size)
{
    const float* inputs   = (const float*)d_in[0];
    const float* codebook = (const float*)d_in[1];
    float* out = (float*)d_out;

    cudaFuncSetAttribute(vq_screen, cudaFuncAttributeMaxDynamicSharedMemorySize, SMEM_DYN);

    vq_csq    <<<NCODES / 256, 256>>>(codebook);
    vq_frag   <<<64, 256>>>(codebook);
    vq_screen <<<NROWS / MROWS, 256, SMEM_DYN>>>(inputs, codebook, out);
    vq_xsq    <<<512, 256>>>(inputs);
    vq_refine <<<8 * RREP, 256>>>(inputs);
    vq_fgather<<<256, 256>>>(codebook, out);
}